// round 17
// baseline (speedup 1.0000x reference)
#include <cuda_runtime.h>
#include <cuda_bf16.h>
#include <cuda_fp16.h>
#include <cstdint>
#include <cstddef>

// Problem constants
#define NW    720
#define LTOK  144
#define DIM   192
#define NHEAD 6
#define HD    32
#define TOW   240
#define SCALE 0.17677669529663687f   // 32^-0.5

// ---------------------------------------------------------------------------
// Scratch
// ---------------------------------------------------------------------------
__device__ __half g_qkv[(size_t)NW * 3 * NHEAD * LTOK * HD];  // fp16 [w][t][h][l][d]
__device__ float g_bias[(size_t)TOW * NHEAD * LTOK * LTOK];   // [tow*6+h][i*144+j]
__device__ __half g_att[(size_t)NW * LTOK * DIM];             // fp16 [w][l][h*32+d]
__device__ __half g_w1h[576 * 192];                           // fp16, Q rows pre-scaled
__device__ __half g_w2h[192 * 192];                           // fp16

__device__ __forceinline__ int posidx(int a, int b) {
    int za = a / 72, ha = (a % 72) / 12, wa = a % 12;
    int zb = b / 72, hb = (b % 72) / 12, wb = b % 12;
    return 828 * (za + 2 * zb) + 23 * (ha + 6 * hb) + (wa - wb + 11);
}

__device__ __forceinline__ uint32_t smem_u32(const void* p) {
    uint32_t a;
    asm("{ .reg .u64 t; cvta.to.shared.u64 t, %1; cvt.u32.u64 %0, t; }"
        : "=r"(a) : "l"(p));
    return a;
}
__device__ __forceinline__ uint32_t packh2(float a, float b) {
    __half2 t = __floats2half2_rn(a, b);
    return *reinterpret_cast<uint32_t*>(&t);
}
__device__ __forceinline__ void ldsm4(uint32_t* r, uint32_t addr) {
    asm volatile("ldmatrix.sync.aligned.m8n8.x4.shared.b16 {%0,%1,%2,%3}, [%4];"
                 : "=r"(r[0]), "=r"(r[1]), "=r"(r[2]), "=r"(r[3]) : "r"(addr));
}
__device__ __forceinline__ void ldsm4t(uint32_t* r, uint32_t addr) {
    asm volatile("ldmatrix.sync.aligned.m8n8.x4.trans.shared.b16 {%0,%1,%2,%3}, [%4];"
                 : "=r"(r[0]), "=r"(r[1]), "=r"(r[2]), "=r"(r[3]) : "r"(addr));
}
__device__ __forceinline__ void mma16816h(float* d, const uint32_t* a, const uint32_t* b) {
    asm volatile(
        "mma.sync.aligned.m16n8k16.row.col.f32.f16.f16.f32 "
        "{%0,%1,%2,%3}, {%4,%5,%6,%7}, {%8,%9}, {%0,%1,%2,%3};"
        : "+f"(d[0]), "+f"(d[1]), "+f"(d[2]), "+f"(d[3])
        : "r"(a[0]), "r"(a[1]), "r"(a[2]), "r"(a[3]), "r"(b[0]), "r"(b[1]));
}
#define CP_ASYNC16(dst, src) \
    asm volatile("cp.async.cg.shared.global [%0], [%1], 16;" \
                 :: "r"(dst), "l"(src) : "memory")
#define CP_COMMIT() asm volatile("cp.async.commit_group;" ::: "memory")
#define CP_WAIT1()  asm volatile("cp.async.wait_group 1;" ::: "memory")
#define CP_WAIT0()  asm volatile("cp.async.wait_group 0;" ::: "memory")

// FFMA-pipe exponential. rel err ~3e-8 for moderate |x|.
__device__ __forceinline__ float exp_fma(float x) {
    float t = x * 1.4426950408889634f;
    float r = rintf(t);
    float f = t - r;
    float p = 1.5423875e-4f;
    p = p * f + 1.3333558e-3f;
    p = p * f + 9.6181291e-3f;
    p = p * f + 5.5504109e-2f;
    p = p * f + 2.4022651e-1f;
    p = p * f + 6.9314718e-1f;
    p = p * f + 1.0f;
    int e = (int)r;
    float s = __int_as_float((e + 127) << 23);
    return s * p;
}

// ---------------------------------------------------------------------------
// K-1: weight prep -> fp16 (w1 Q-rows pre-scaled).
// ---------------------------------------------------------------------------
__global__ void wsplit_kernel(const float* __restrict__ w1,
                              const float* __restrict__ w2) {
    const int row = blockIdx.x, col = threadIdx.x;
    if (row < 576) {
        float v = w1[row * 192 + col];
        if (row < 192) v *= SCALE;
        g_w1h[row * 192 + col] = __float2half(v);
    } else {
        int r = row - 576;
        g_w2h[r * 192 + col] = __float2half(w2[r * 192 + col]);
    }
}

// ---------------------------------------------------------------------------
// K0: bias gather/transpose
// ---------------------------------------------------------------------------
__global__ void bias_gather_kernel(const float* __restrict__ table) {
    __shared__ float tile[32][241];
    const int ij0 = blockIdx.x * 32;
    const int tt0 = blockIdx.y * 240;
    const int tid = threadIdx.x;

    for (int e = tid; e < 32 * 240; e += 256) {
        int ii = e / 240, tt = e % 240;
        int ij = ij0 + ii;
        int a = ij / LTOK, b = ij % LTOK;
        tile[ii][tt] = table[(size_t)posidx(a, b) * (TOW * NHEAD) + tt0 + tt];
    }
    __syncthreads();
    for (int e = tid; e < 32 * 240; e += 256) {
        int tt = e / 32, c = e % 32;
        g_bias[(size_t)(tt0 + tt) * (LTOK * LTOK) + ij0 + c] = tile[c][tt];
    }
}

// ---------------------------------------------------------------------------
// K1: qkv GEMM, single-term fp16 (R16 version).
// ---------------------------------------------------------------------------
#define ROWB  400
#define QA_OFF 0
#define QB_OFF (128 * ROWB)                  // 51200
#define QKV_SMEM (QB_OFF + 64 * ROWB)        // 76800

__global__ __launch_bounds__(256)
void tc_gemm_qkv(const float* __restrict__ x, const float* __restrict__ bias) {
    extern __shared__ __align__(16) char sm[];
    const uint32_t smb = smem_u32(sm);
    const int tid = threadIdx.x;
    const int wid = tid >> 5, lane = tid & 31;
    const int m0 = blockIdx.x * 128;

    for (int e = tid; e < 128 * 48; e += 256) {
        int m = e / 48, k4 = e % 48;
        float4 v = *reinterpret_cast<const float4*>(x + (size_t)(m0 + m) * 192 + k4 * 4);
        *reinterpret_cast<uint2*>(sm + QA_OFF + m * ROWB + k4 * 8) =
            make_uint2(packh2(v.x, v.y), packh2(v.z, v.w));
    }

    const int wm = wid & 3, wn = wid >> 2;
    const int gid = lane >> 2, qid = lane & 3;
    const int g = lane >> 3, r8 = lane & 7;

    size_t rowbase[2][2];
#pragma unroll
    for (int mt = 0; mt < 2; mt++)
#pragma unroll
        for (int half = 0; half < 2; half++) {
            const int m = m0 + wm * 32 + mt * 16 + gid + half * 8;
            const int w = m / LTOK, l = m % LTOK;
            rowbase[mt][half] = (size_t)w * (3 * NHEAD * LTOK * HD) + l * HD;
        }

    for (int nt = 0; nt < 9; nt++) {
        if (nt) __syncthreads();
        for (int e = tid; e < 64 * 24; e += 256) {
            int n = e / 24, c = e % 24;
            *reinterpret_cast<uint4*>(sm + QB_OFF + n * ROWB + c * 16) =
                *reinterpret_cast<const uint4*>(g_w1h + (size_t)(nt * 64 + n) * 192 + c * 8);
        }
        __syncthreads();

        float acc[2][4][4];
#pragma unroll
        for (int i = 0; i < 2; i++)
#pragma unroll
            for (int j = 0; j < 4; j++)
#pragma unroll
                for (int c = 0; c < 4; c++) acc[i][j][c] = 0.0f;

#pragma unroll 3
        for (int ks = 0; ks < 12; ks++) {
            const int k0 = ks * 16;
            uint32_t aa[2][4];
#pragma unroll
            for (int mt = 0; mt < 2; mt++) {
                uint32_t row = wm * 32 + mt * 16 + r8 + (g & 1) * 8;
                uint32_t koff = (k0 + (g >> 1) * 8) * 2;
                ldsm4(aa[mt], smb + QA_OFF + row * ROWB + koff);
            }
            uint32_t bb[4][2];
#pragma unroll
            for (int pr = 0; pr < 2; pr++) {
                uint32_t row = wn * 32 + pr * 16 + r8 + (g >> 1) * 8;
                uint32_t koff = (k0 + (g & 1) * 8) * 2;
                uint32_t tb[4];
                ldsm4(tb, smb + QB_OFF + row * ROWB + koff);
                bb[pr * 2 + 0][0] = tb[0]; bb[pr * 2 + 0][1] = tb[1];
                bb[pr * 2 + 1][0] = tb[2]; bb[pr * 2 + 1][1] = tb[3];
            }
#pragma unroll
            for (int mt = 0; mt < 2; mt++)
#pragma unroll
                for (int ntn = 0; ntn < 4; ntn++)
                    mma16816h(acc[mt][ntn], aa[mt], bb[ntn]);
        }

        const int cbase = nt * 64 + wn * 32;
#pragma unroll
        for (int ntn = 0; ntn < 4; ntn++) {
            const int c = cbase + ntn * 8 + qid * 2;
            float2 bv = *reinterpret_cast<const float2*>(bias + c);
            if (c < 192) { bv.x *= SCALE; bv.y *= SCALE; }
            const int t = c / DIM, hh = (c % DIM) / HD, d = c % HD;
            const size_t coff = (size_t)t * (NHEAD * LTOK * HD) + hh * (LTOK * HD) + d;
#pragma unroll
            for (int mt = 0; mt < 2; mt++) {
#pragma unroll
                for (int half = 0; half < 2; half++) {
                    *reinterpret_cast<uint32_t*>(g_qkv + rowbase[mt][half] + coff)
                        = packh2(acc[mt][ntn][half * 2 + 0] + bv.x,
                                 acc[mt][ntn][half * 2 + 1] + bv.y);
                }
            }
        }
    }
}

// ---------------------------------------------------------------------------
// K3: out-proj GEMM, single-term fp16 (R16 version).
// ---------------------------------------------------------------------------
#define OA_OFF 0
#define OB_OFF (128 * ROWB)
#define OUT_SMEM (OB_OFF + 64 * ROWB)        // 76800

__global__ __launch_bounds__(256)
void tc_gemm_out(const float* __restrict__ bias, float* __restrict__ C) {
    extern __shared__ __align__(16) char sm[];
    const uint32_t smb = smem_u32(sm);
    const int tid = threadIdx.x;
    const int wid = tid >> 5, lane = tid & 31;
    const int m0 = blockIdx.x * 128;

    for (int e = tid; e < 128 * 24; e += 256) {
        int m = e / 24, c4 = e % 24;
        *reinterpret_cast<uint4*>(sm + OA_OFF + m * ROWB + c4 * 16) =
            *reinterpret_cast<const uint4*>(g_att + (size_t)(m0 + m) * 192 + c4 * 8);
    }

    const int wm = wid & 3, wn = wid >> 2;
    const int gid = lane >> 2, qid = lane & 3;
    const int g = lane >> 3, r8 = lane & 7;

    for (int nt = 0; nt < 3; nt++) {
        if (nt) __syncthreads();
        for (int e = tid; e < 64 * 24; e += 256) {
            int n = e / 24, c = e % 24;
            *reinterpret_cast<uint4*>(sm + OB_OFF + n * ROWB + c * 16) =
                *reinterpret_cast<const uint4*>(g_w2h + (size_t)(nt * 64 + n) * 192 + c * 8);
        }
        __syncthreads();

        float acc[2][4][4];
#pragma unroll
        for (int i = 0; i < 2; i++)
#pragma unroll
            for (int j = 0; j < 4; j++)
#pragma unroll
                for (int c = 0; c < 4; c++) acc[i][j][c] = 0.0f;

#pragma unroll 3
        for (int ks = 0; ks < 12; ks++) {
            const int k0 = ks * 16;
            uint32_t aa[2][4];
#pragma unroll
            for (int mt = 0; mt < 2; mt++) {
                uint32_t row = wm * 32 + mt * 16 + r8 + (g & 1) * 8;
                uint32_t koff = (k0 + (g >> 1) * 8) * 2;
                ldsm4(aa[mt], smb + OA_OFF + row * ROWB + koff);
            }
            uint32_t bb[4][2];
#pragma unroll
            for (int pr = 0; pr < 2; pr++) {
                uint32_t row = wn * 32 + pr * 16 + r8 + (g >> 1) * 8;
                uint32_t koff = (k0 + (g & 1) * 8) * 2;
                uint32_t tb[4];
                ldsm4(tb, smb + OB_OFF + row * ROWB + koff);
                bb[pr * 2 + 0][0] = tb[0]; bb[pr * 2 + 0][1] = tb[1];
                bb[pr * 2 + 1][0] = tb[2]; bb[pr * 2 + 1][1] = tb[3];
            }
#pragma unroll
            for (int mt = 0; mt < 2; mt++)
#pragma unroll
                for (int ntn = 0; ntn < 4; ntn++)
                    mma16816h(acc[mt][ntn], aa[mt], bb[ntn]);
        }

        const int cbase = nt * 64 + wn * 32;
#pragma unroll
        for (int ntn = 0; ntn < 4; ntn++) {
            const int c = cbase + ntn * 8 + qid * 2;
            const float2 bv = *reinterpret_cast<const float2*>(bias + c);
#pragma unroll
            for (int mt = 0; mt < 2; mt++) {
#pragma unroll
                for (int half = 0; half < 2; half++) {
                    const int m = m0 + wm * 32 + mt * 16 + gid + half * 8;
                    *reinterpret_cast<float2*>(C + (size_t)m * DIM + c) =
                        make_float2(acc[mt][ntn][half * 2 + 0] + bv.x,
                                    acc[mt][ntn][half * 2 + 1] + bv.y);
                }
            }
        }
    }
}

// ---------------------------------------------------------------------------
// K2: HMMA fp16 attention; mask prefetch + cp.async double-buffered Q/K/V.
// smem: 2 x (Q|K|V tile, 34560B) + bias (42048B) = 111168B -> 2 CTA/SM.
// Fill for wrep+1 is issued before computing wrep; wait_group(1) keeps one
// group in flight. Buffer reuse is safe: buf[(wrep+1)&1] was last consumed
// in wrep-1, whose post-compute __syncthreads precedes these cp.asyncs.
// ---------------------------------------------------------------------------
#define AROW 80
#define TILE3 (3 * LTOK * AROW)              // 34560
#define SB_OFF (2 * TILE3)                   // 69120
#define SBSTRIDE 146
#define ATTN_SMEM (SB_OFF + LTOK * SBSTRIDE * 2)   // 111168

__global__ __launch_bounds__(288)
void attn_mma_kernel(const float* __restrict__ mask) {
    extern __shared__ __align__(16) char sm[];
    const int bx = blockIdx.x;
    const int tow = bx / NHEAD;
    const int h = bx % NHEAD;
    const int tid = threadIdx.x;
    const int warp = tid >> 5, lane = tid & 31;
    const int gid = lane >> 2, qid = lane & 3;
    const int g = lane >> 3, r8 = lane & 7;
    const uint32_t smb = smem_u32(sm);
    const int r0 = warp * 16;

    // bias -> smem fp16 (once per block)
    const float* bias_base = g_bias + ((size_t)tow * NHEAD + h) * (LTOK * LTOK);
    for (int e = tid; e < LTOK * 72; e += 288) {
        int row = e / 72, c2 = e % 72;
        float2 v = *reinterpret_cast<const float2*>(bias_base + row * LTOK + c2 * 2);
        *reinterpret_cast<uint32_t*>(sm + SB_OFF + (row * SBSTRIDE + c2 * 2) * 2) =
            packh2(v.x, v.y);
    }

    const __half* sb0 = reinterpret_cast<const __half*>(sm + SB_OFF) + (r0 + gid) * SBSTRIDE;
    const __half* sb1 = sb0 + 8 * SBSTRIDE;

    // async fill of Q/K/V tile for window wrep_t into buffer base bb
    auto issue_fill = [&](int wrep_t, uint32_t bb) {
        const int w = tow + wrep_t * TOW;
        const __half* qg = g_qkv + (((size_t)w * 3 + 0) * NHEAD + h) * (LTOK * HD);
        const __half* kg = g_qkv + (((size_t)w * 3 + 1) * NHEAD + h) * (LTOK * HD);
        const __half* vg = g_qkv + (((size_t)w * 3 + 2) * NHEAD + h) * (LTOK * HD);
        for (int e = tid; e < LTOK * 4; e += 288) {
            int row = e >> 2, c4 = e & 3;
            uint32_t off = row * AROW + c4 * 16;
            CP_ASYNC16(bb + off, qg + row * HD + c4 * 8);
            CP_ASYNC16(bb + LTOK * AROW + off, kg + row * HD + c4 * 8);
            CP_ASYNC16(bb + 2 * LTOK * AROW + off, vg + row * HD + c4 * 8);
        }
    };

    issue_fill(0, smb);
    CP_COMMIT();

    for (int wrep = 0; wrep < 3; wrep++) {
        const int w = tow + wrep * TOW;
        const uint32_t bb = smb + (wrep & 1) * TILE3;

        if (wrep < 2) {
            issue_fill(wrep + 1, smb + ((wrep + 1) & 1) * TILE3);
            CP_COMMIT();
            CP_WAIT1();
        } else {
            CP_WAIT0();
        }
        __syncthreads();

        uint32_t aq[2][4];
#pragma unroll
        for (int ks = 0; ks < 2; ks++)
            ldsm4(aq[ks], bb + (r0 + r8 + (g & 1) * 8) * AROW
                              + (ks * 16 + (g >> 1) * 8) * 2);

        float oacc[4][4];
#pragma unroll
        for (int i = 0; i < 4; i++)
#pragma unroll
            for (int c = 0; c < 4; c++) oacc[i][c] = 0.0f;
        float ls0 = 0.0f, ls1 = 0.0f;

        const float* mrow0 = mask + ((size_t)w * LTOK + r0 + gid) * LTOK + qid * 2;
        const float* mrow1 = mrow0 + 8 * LTOK;

        float2 pm[4];
        pm[0] = *reinterpret_cast<const float2*>(mrow0);
        pm[1] = *reinterpret_cast<const float2*>(mrow0 + 8);
        pm[2] = *reinterpret_cast<const float2*>(mrow1);
        pm[3] = *reinterpret_cast<const float2*>(mrow1 + 8);

#pragma unroll 3
        for (int nc = 0; nc < 9; nc++) {
            float2 cm0 = pm[0], cm1 = pm[1], cm2 = pm[2], cm3 = pm[3];
            if (nc < 8) {
                const int ncol = (nc + 1) * 16;
                pm[0] = *reinterpret_cast<const float2*>(mrow0 + ncol);
                pm[1] = *reinterpret_cast<const float2*>(mrow0 + ncol + 8);
                pm[2] = *reinterpret_cast<const float2*>(mrow1 + ncol);
                pm[3] = *reinterpret_cast<const float2*>(mrow1 + ncol + 8);
            }

            float sacc[2][4] = {{0.f, 0.f, 0.f, 0.f}, {0.f, 0.f, 0.f, 0.f}};
#pragma unroll
            for (int ks = 0; ks < 2; ks++) {
                uint32_t kb[4];
                ldsm4(kb, bb + LTOK * AROW + (nc * 16 + r8 + (g >> 1) * 8) * AROW
                              + (ks * 16 + (g & 1) * 8) * 2);
                mma16816h(sacc[0], aq[ks], kb + 0);
                mma16816h(sacc[1], aq[ks], kb + 2);
            }

            uint32_t pa[4];
            {
                int col0 = nc * 16 + qid * 2;
                float2 b00 = __half22float2(*reinterpret_cast<const __half2*>(sb0 + col0));
                float2 b01 = __half22float2(*reinterpret_cast<const __half2*>(sb0 + col0 + 8));
                float2 b10 = __half22float2(*reinterpret_cast<const __half2*>(sb1 + col0));
                float2 b11 = __half22float2(*reinterpret_cast<const __half2*>(sb1 + col0 + 8));
                float p0 = exp_fma(sacc[0][0] + b00.x + cm0.x);
                float p1 = exp_fma(sacc[0][1] + b00.y + cm0.y);
                float p2 = exp_fma(sacc[0][2] + b10.x + cm2.x);
                float p3 = exp_fma(sacc[0][3] + b10.y + cm2.y);
                float p4 = exp_fma(sacc[1][0] + b01.x + cm1.x);
                float p5 = exp_fma(sacc[1][1] + b01.y + cm1.y);
                float p6 = exp_fma(sacc[1][2] + b11.x + cm3.x);
                float p7 = exp_fma(sacc[1][3] + b11.y + cm3.y);
                ls0 += p0 + p1 + p4 + p5;
                ls1 += p2 + p3 + p6 + p7;
                pa[0] = packh2(p0, p1);
                pa[1] = packh2(p2, p3);
                pa[2] = packh2(p4, p5);
                pa[3] = packh2(p6, p7);
            }
#pragma unroll
            for (int dh = 0; dh < 2; dh++) {
                uint32_t vb[4];
                ldsm4t(vb, bb + 2 * LTOK * AROW + (nc * 16 + (g & 1) * 8 + r8) * AROW
                               + (dh * 16 + (g >> 1) * 8) * 2);
                mma16816h(oacc[dh * 2 + 0], pa, vb + 0);
                mma16816h(oacc[dh * 2 + 1], pa, vb + 2);
            }
        }

        ls0 += __shfl_xor_sync(0xFFFFFFFFu, ls0, 1);
        ls0 += __shfl_xor_sync(0xFFFFFFFFu, ls0, 2);
        ls1 += __shfl_xor_sync(0xFFFFFFFFu, ls1, 1);
        ls1 += __shfl_xor_sync(0xFFFFFFFFu, ls1, 2);
        const float ri0 = 1.0f / ls0;
        const float ri1 = 1.0f / ls1;

        __half* ob0 = g_att + ((size_t)w * LTOK + r0 + gid) * DIM + h * HD;
        __half* ob1 = ob0 + 8 * DIM;
#pragma unroll
        for (int dt = 0; dt < 4; dt++) {
            *reinterpret_cast<uint32_t*>(ob0 + dt * 8 + qid * 2) =
                packh2(oacc[dt][0] * ri0, oacc[dt][1] * ri0);
            *reinterpret_cast<uint32_t*>(ob1 + dt * 8 + qid * 2) =
                packh2(oacc[dt][2] * ri1, oacc[dt][3] * ri1);
        }
        __syncthreads();
    }
}

// ---------------------------------------------------------------------------
// Launch. Inputs: 0 x, 1 mask, 2 w1, 3 b1, 4 w2, 5 b2, 6 bias_table
// ---------------------------------------------------------------------------
extern "C" void kernel_launch(void* const* d_in, const int* in_sizes, int n_in,
                              void* d_out, int out_size) {
    const float* x     = (const float*)d_in[0];
    const float* mask  = (const float*)d_in[1];
    const float* w1    = (const float*)d_in[2];
    const float* b1    = (const float*)d_in[3];
    const float* w2    = (const float*)d_in[4];
    const float* b2    = (const float*)d_in[5];
    const float* table = (const float*)d_in[6];
    float* out = (float*)d_out;

    static bool attr_done = false;
    if (!attr_done) {
        cudaFuncSetAttribute(tc_gemm_qkv,
                             cudaFuncAttributeMaxDynamicSharedMemorySize, QKV_SMEM);
        cudaFuncSetAttribute(tc_gemm_out,
                             cudaFuncAttributeMaxDynamicSharedMemorySize, OUT_SMEM);
        cudaFuncSetAttribute(attn_mma_kernel,
                             cudaFuncAttributeMaxDynamicSharedMemorySize, ATTN_SMEM);
        attr_done = true;
    }

    wsplit_kernel<<<768, 192>>>(w1, w2);
    bias_gather_kernel<<<dim3(648, 6), 256>>>(table);
    tc_gemm_qkv<<<810, 256, QKV_SMEM>>>(x, b1);
    attn_mma_kernel<<<TOW * NHEAD, 288, ATTN_SMEM>>>(mask);
    tc_gemm_out<<<810, 256, OUT_SMEM>>>(b2, out);
}